// round 2
// baseline (speedup 1.0000x reference)
#include <cuda_runtime.h>
#include <cuda_bf16.h>
#include <math.h>

// Problem constants
#define B  2
#define N  512
#define FI 256
#define FO 128
#define ALPHA 0.2f

// e-kernel tiling
#define TJ 32
#define TI 32
#define NPART (B * (N/TI) * (N/TJ))   // 2*16*16 = 512

// output-kernel tiling
#define ROWS_D 8                       // rows per CTA in final kernel

// Scratch (no allocations allowed -> device globals)
__device__ float g_Wh[B * N * FO];     // 512 KB
__device__ float g_e [B * N * N];      // 2 MB
__device__ float g_part[NPART];
__device__ float g_inv[1];

__device__ __forceinline__ float lrelu(float x) {
    // alpha < 1: max(x, alpha*x) == leaky_relu(x)
    return fmaxf(x, ALPHA * x);
}

// ---------------------------------------------------------------------------
// Kernel A: Wh = x @ W      grid: B*N blocks, 128 threads (one output o each)
// ---------------------------------------------------------------------------
__global__ void k_gemm(const float* __restrict__ x, const float* __restrict__ W) {
    const int row = blockIdx.x;          // 0 .. B*N-1
    const int o   = threadIdx.x;         // 0 .. 127

    __shared__ float xs[FI];
    #pragma unroll
    for (int f = threadIdx.x; f < FI; f += FO)
        xs[f] = x[row * FI + f];
    __syncthreads();

    float acc = 0.f;
    #pragma unroll 8
    for (int f = 0; f < FI; f++)
        acc = fmaf(xs[f], W[f * FO + o], acc);

    g_Wh[row * FO + o] = acc;
}

// ---------------------------------------------------------------------------
// Kernel B: e[b,i,j] = sum_o a_o * lrelu(Wh[b,i,o] + Wh[b,j,o])
//           + per-block partial sum of e^2 (for the global norm)
// grid: (N/TJ, N/TI, B), block: (32, 8) -> each thread does 4 i's, 1 j
// ---------------------------------------------------------------------------
__global__ void k_edges(const float* __restrict__ a_fc) {
    const int b  = blockIdx.z;
    const int it = blockIdx.y * TI;
    const int jt = blockIdx.x * TJ;
    const int tx = threadIdx.x;          // j lane 0..31
    const int ty = threadIdx.y;          // 0..7
    const int tid = ty * 32 + tx;

    // padded float4 tiles: row stride 33 float4 (=132 floats) -> conflict free
    __shared__ float4 tIs[TI * 33];
    __shared__ float4 tJs[TJ * 33];
    __shared__ float4 aS[FO / 4];

    const float4* Wh4 = reinterpret_cast<const float4*>(g_Wh);
    const float4* a4  = reinterpret_cast<const float4*>(a_fc);

    if (tid < FO / 4) aS[tid] = a4[tid];

    // load both 32x128 tiles (32 rows x 32 float4 each)
    #pragma unroll
    for (int p = 0; p < 4; p++) {
        int idx = tid + 256 * p;         // 0..1023
        int r = idx >> 5, c = idx & 31;
        tIs[r * 33 + c] = Wh4[(b * N + it + r) * (FO / 4) + c];
        tJs[r * 33 + c] = Wh4[(b * N + jt + r) * (FO / 4) + c];
    }
    __syncthreads();

    float acc[4] = {0.f, 0.f, 0.f, 0.f};

    #pragma unroll 4
    for (int oc = 0; oc < FO / 4; oc++) {
        const float4 wj = tJs[tx * 33 + oc];    // lane-varying, conflict-free
        const float4 av = aS[oc];               // broadcast
        #pragma unroll
        for (int k = 0; k < 4; k++) {
            const float4 wi = tIs[(ty + 8 * k) * 33 + oc];  // warp broadcast
            float s;
            s = acc[k];
            s = fmaf(lrelu(wi.x + wj.x), av.x, s);
            s = fmaf(lrelu(wi.y + wj.y), av.y, s);
            s = fmaf(lrelu(wi.z + wj.z), av.z, s);
            s = fmaf(lrelu(wi.w + wj.w), av.w, s);
            acc[k] = s;
        }
    }

    float ss = 0.f;
    #pragma unroll
    for (int k = 0; k < 4; k++) {
        const int i = it + ty + 8 * k;
        g_e[(b * N + i) * N + jt + tx] = acc[k];
        ss = fmaf(acc[k], acc[k], ss);
    }

    // deterministic block reduction of ss
    #pragma unroll
    for (int off = 16; off > 0; off >>= 1)
        ss += __shfl_xor_sync(0xFFFFFFFFu, ss, off);

    __shared__ float wsum[8];
    if (tx == 0) wsum[ty] = ss;
    __syncthreads();
    if (tid == 0) {
        float t = 0.f;
        #pragma unroll
        for (int w = 0; w < 8; w++) t += wsum[w];
        g_part[(blockIdx.z * (N/TI) + blockIdx.y) * (N/TJ) + blockIdx.x] = t;
    }
}

// ---------------------------------------------------------------------------
// Kernel C: reduce partials -> g_inv = 1/sqrt(sum e^2)   (deterministic tree)
// ---------------------------------------------------------------------------
__global__ void k_norm() {
    __shared__ float sm[NPART];
    const int t = threadIdx.x;
    sm[t] = g_part[t];
    __syncthreads();
    #pragma unroll
    for (int s = NPART / 2; s > 0; s >>= 1) {
        if (t < s) sm[t] += sm[t + s];
        __syncthreads();
    }
    if (t == 0) g_inv[0] = 1.0f / sqrtf(sm[0]);
}

// ---------------------------------------------------------------------------
// Kernel D: per-row mask + softmax, then h' = att @ Wh, then ELU
// grid: (N/ROWS_D, B), block: (128, 2)
//   phase 1: 8 warps, one row each -> unnormalized exp weights in smem
//   phase 2: thread (o=tx, ty) accumulates 4 rows over all j
// ---------------------------------------------------------------------------
__global__ void k_out(const int* __restrict__ adj, float* __restrict__ out) {
    const int b  = blockIdx.y;
    const int i0 = blockIdx.x * ROWS_D;
    const int tx = threadIdx.x;
    const int ty = threadIdx.y;
    const int tid  = ty * 128 + tx;
    const int warp = tid >> 5;
    const int lane = tid & 31;

    __shared__ float att[ROWS_D][N];   // unnormalized softmax weights
    __shared__ float rnorm[ROWS_D];    // 1/rowsum

    const float inv = g_inv[0];

    // ---- phase 1: softmax weights for row (i0 + warp) ----
    {
        const int i = i0 + warp;
        const float* erow = &g_e[(b * N + i) * N];
        const int*   arow = &adj[(b * N + i) * N];

        float ev[N / 32];
        float mx = -INFINITY;
        #pragma unroll
        for (int m = 0; m < N / 32; m++) {
            const int j = lane + 32 * m;
            float v = erow[j] * inv;
            if (arow[j] == 0) v = -INFINITY;
            ev[m] = v;
            mx = fmaxf(mx, v);
        }
        #pragma unroll
        for (int off = 16; off > 0; off >>= 1)
            mx = fmaxf(mx, __shfl_xor_sync(0xFFFFFFFFu, mx, off));

        float sum = 0.f;
        #pragma unroll
        for (int m = 0; m < N / 32; m++) {
            const int j = lane + 32 * m;
            const float p = expf(ev[m] - mx);   // exp(-inf)=0 for masked
            att[warp][j] = p;
            sum += p;
        }
        #pragma unroll
        for (int off = 16; off > 0; off >>= 1)
            sum += __shfl_xor_sync(0xFFFFFFFFu, sum, off);
        if (lane == 0) rnorm[warp] = 1.0f / sum;
    }
    __syncthreads();

    // ---- phase 2: h'[i, o] = sum_j att[i][j] * Wh[b, j, o] ----
    const int r0 = ty * 4;
    const int o  = tx;
    float acc[4] = {0.f, 0.f, 0.f, 0.f};

    const float* WhB = &g_Wh[b * N * FO];
    const float4 (*att4)[N / 4] = reinterpret_cast<const float4 (*)[N / 4]>(att);

    #pragma unroll 4
    for (int jc = 0; jc < N / 4; jc++) {
        const int j = jc * 4;
        const float w0 = WhB[(j + 0) * FO + o];
        const float w1 = WhB[(j + 1) * FO + o];
        const float w2 = WhB[(j + 2) * FO + o];
        const float w3 = WhB[(j + 3) * FO + o];
        #pragma unroll
        for (int r = 0; r < 4; r++) {
            const float4 a4 = att4[r0 + r][jc];   // warp broadcast
            float s = acc[r];
            s = fmaf(a4.x, w0, s);
            s = fmaf(a4.y, w1, s);
            s = fmaf(a4.z, w2, s);
            s = fmaf(a4.w, w3, s);
            acc[r] = s;
        }
    }

    #pragma unroll
    for (int r = 0; r < 4; r++) {
        const int i = i0 + r0 + r;
        float v = acc[r] * rnorm[r0 + r];
        v = (v > 0.f) ? v : expm1f(v);          // ELU (alpha=1)
        out[(b * N + i) * FO + o] = v;
    }
}

// ---------------------------------------------------------------------------
extern "C" void kernel_launch(void* const* d_in, const int* in_sizes, int n_in,
                              void* d_out, int out_size) {
    const float* x    = (const float*)d_in[0];   // [B,N,FI]
    const int*   adj  = (const int*)  d_in[1];   // [B,N,N]
    const float* W    = (const float*)d_in[2];   // [FI,FO]
    const float* a_fc = (const float*)d_in[3];   // [FO]
    float* out = (float*)d_out;                  // [B,N,FO]

    k_gemm <<< B * N, FO >>>(x, W);
    k_edges<<< dim3(N/TJ, N/TI, B), dim3(32, 8) >>>(a_fc);
    k_norm <<< 1, NPART >>>();
    k_out  <<< dim3(N/ROWS_D, B), dim3(128, 2) >>>(adj, out);
}